// round 9
// baseline (speedup 1.0000x reference)
#include <cuda_runtime.h>
#include <cstdint>
#include <math_constants.h>

// ---------------------------------------------------------------------------
// MDescAug: per-query candidate reranking with descriptor augmentation.
//   X: [50000,512] f32,  Q: [100,512] f32,  ranks: [50000,100] i32/i64 (probed)
// Output f32 concat: rerank_final[100,400], res_top[100,400], pre[100,400],
//                    x_dba[100,400,512]
// Strategy: 1-term bf16 tensor GEMM -> approx S (selection only), approx
// top-16 superset, exact serial-fp32 repair of 16 dots -> bitwise reference
// top-10. Round 9: exact_kernel loads candidate rows in 128B chunks
// (8x fewer L1tex wavefronts).
// ---------------------------------------------------------------------------

#define NDB  50000
#define NQ   100
#define DIM  512
#define MM   400
#define MPAD 448              // 7 * 64, zero-padded rows
#define KTOP 10
#define NCAND 16
#define BETA 0.15f

#define OFF_RERANK 0
#define OFF_RESTOP 40000
#define OFF_PRE    80000
#define OFF_XDBA   120000
#define FULL_OUT   20600000

// Scratch (device globals; no allocation allowed)
__device__ float g_Xs[(size_t)NQ * MPAD * DIM];   // gathered (padded)
__device__ float g_S[(size_t)NQ * MM * MM];       // approx similarity
__device__ int   g_rt[NQ * MM];
__device__ int   g_cand[NQ * MM * NCAND];
__device__ int   g_idx[NQ * MM * KTOP];
__device__ float g_vals[NQ * MM * KTOP];
__device__ float g_restop[NQ * MM];
__device__ int   g_is64;

// ---- order-preserving float<->uint ------------------------------------------
__device__ __forceinline__ unsigned int ordf(float f) {
    unsigned int u = __float_as_uint(f);
    return (u & 0x80000000u) ? ~u : (u | 0x80000000u);
}
__device__ __forceinline__ float unordf(unsigned int o) {
    return __uint_as_float((o & 0x80000000u) ? (o & 0x7FFFFFFFu) : ~o);
}
__device__ __forceinline__ unsigned long long pack_key(float v, int idx) {
    return ((unsigned long long)ordf(v) << 32) |
           (unsigned long long)(0xFFFFFFFFu - (unsigned int)idx);
}

// ---- probe: int64 vs int32 ranks --------------------------------------------
__global__ void probe_kernel(const int* __restrict__ r) {
    __shared__ int cnt;
    if (threadIdx.x == 0) cnt = 0;
    __syncthreads();
    int nz = 0;
    for (int i = threadIdx.x; i < 1024; i += blockDim.x)
        nz += (r[2 * i + 1] != 0);
    atomicAdd(&cnt, nz);
    __syncthreads();
    if (threadIdx.x == 0) g_is64 = (cnt < 100) ? 1 : 0;
}

// ---- gather Xs[q][m][:] = X[ranks[m][q]][:]; zero-pad rows 400..447 ---------
__global__ __launch_bounds__(128) void gather_kernel(const float* __restrict__ X,
                                                     const void* __restrict__ ranks) {
    int m = blockIdx.x, q = blockIdx.y, tid = threadIdx.x;
    float4* dst = (float4*)(g_Xs + ((size_t)q * MPAD + m) * DIM);
    if (m >= MM) {
        dst[tid] = make_float4(0.f, 0.f, 0.f, 0.f);
        return;
    }
    int rid;
    if (g_is64) rid = (int)((const long long*)ranks)[(size_t)m * NQ + q];
    else        rid = ((const int*)ranks)[(size_t)m * NQ + q];
    if (tid == 0) g_rt[q * MM + m] = rid;
    const float4* src = (const float4*)(X + (size_t)rid * DIM);
    dst[tid] = src[tid];
}

// ---- bf16 pack: (x0, x1) -> bf16x2 ------------------------------------------
__device__ __forceinline__ unsigned cvt_bf2(float x0, float x1) {
    unsigned h;
    asm("cvt.rn.bf16x2.f32 %0, %1, %2;" : "=r"(h) : "f"(x1), "f"(x0));
    return h;
}

__device__ __forceinline__ void mma_bf16(float* c, const unsigned* a, const unsigned* b) {
    asm volatile(
        "mma.sync.aligned.m16n8k16.row.col.f32.bf16.bf16.f32 "
        "{%0,%1,%2,%3}, {%4,%5,%6,%7}, {%8,%9}, {%0,%1,%2,%3};\n"
        : "+f"(c[0]), "+f"(c[1]), "+f"(c[2]), "+f"(c[3])
        : "r"(a[0]), "r"(a[1]), "r"(a[2]), "r"(a[3]), "r"(b[0]), "r"(b[1]));
}

// ---- batched symmetric approx GEMM, plain bf16 ------------------------------
// Block tile 64x64, BK=32, 128 threads (4 warps, 2x2 of 32x32 warp tiles).
#define LDW 18   // smem row stride in 32-bit words (36 halves); conflict-free
__global__ __launch_bounds__(128) void gemm_kernel() {
    __shared__ unsigned Ah[64 * LDW];
    __shared__ unsigned Bh[64 * LDW];

    int p = blockIdx.x, q = blockIdx.y;
    int bi = 0, bj = 0;
    {
        int t = 0;
        #pragma unroll
        for (int i = 0; i < 7; i++) {
            int c = 7 - i;
            if (p < t + c) { bi = i; bj = i + (p - t); break; }
            t += c;
        }
    }
    const float* Xq = g_Xs + (size_t)q * MPAD * DIM;
    const float* Ap = Xq + (size_t)bi * 64 * DIM;
    const float* Bp = Xq + (size_t)bj * 64 * DIM;

    int tid = threadIdx.x;
    int warp = tid >> 5, lane = tid & 31;
    int wm = warp >> 1, wn = warp & 1;
    int lr = lane >> 2, lc = lane & 3;

    int srow = tid >> 1, sh = tid & 1;
    const float4* Ag = (const float4*)(Ap + (size_t)srow * DIM + sh * 16);
    const float4* Bg = (const float4*)(Bp + (size_t)srow * DIM + sh * 16);

    float acc[2][4][4];
    #pragma unroll
    for (int mi = 0; mi < 2; mi++)
        #pragma unroll
        for (int ni = 0; ni < 4; ni++)
            #pragma unroll
            for (int e = 0; e < 4; e++) acc[mi][ni][e] = 0.0f;

    float4 pA[4], pB[4];
    #pragma unroll
    for (int j = 0; j < 4; j++) { pA[j] = Ag[j]; pB[j] = Bg[j]; }

    for (int ch = 0; ch < 16; ch++) {
        __syncthreads();
        #pragma unroll
        for (int j = 0; j < 4; j++) {
            int w = srow * LDW + sh * 8 + j * 2;
            Ah[w]     = cvt_bf2(pA[j].x, pA[j].y);
            Ah[w + 1] = cvt_bf2(pA[j].z, pA[j].w);
            Bh[w]     = cvt_bf2(pB[j].x, pB[j].y);
            Bh[w + 1] = cvt_bf2(pB[j].z, pB[j].w);
        }
        __syncthreads();
        if (ch < 15) {
            int o = (ch + 1) * 8;
            #pragma unroll
            for (int j = 0; j < 4; j++) { pA[j] = Ag[o + j]; pB[j] = Bg[o + j]; }
        }
        #pragma unroll
        for (int kc = 0; kc < 2; kc++) {
            int cb = kc * 8 + lc;
            unsigned ah[2][4];
            #pragma unroll
            for (int mi = 0; mi < 2; mi++) {
                int r = wm * 32 + mi * 16 + lr;
                ah[mi][0] = Ah[r * LDW + cb];
                ah[mi][1] = Ah[(r + 8) * LDW + cb];
                ah[mi][2] = Ah[r * LDW + cb + 4];
                ah[mi][3] = Ah[(r + 8) * LDW + cb + 4];
            }
            #pragma unroll
            for (int ni = 0; ni < 4; ni++) {
                int n = wn * 32 + ni * 8 + lr;
                unsigned bh[2] = {Bh[n * LDW + cb], Bh[n * LDW + cb + 4]};
                #pragma unroll
                for (int mi = 0; mi < 2; mi++)
                    mma_bf16(acc[mi][ni], ah[mi], bh);
            }
        }
    }

    float* S = g_S + (size_t)q * MM * MM;
    int lc2 = lc * 2;
    #pragma unroll
    for (int mi = 0; mi < 2; mi++) {
        #pragma unroll
        for (int ni = 0; ni < 4; ni++) {
            int r0 = bi * 64 + wm * 32 + mi * 16 + lr;
            int c0 = bj * 64 + wn * 32 + ni * 8 + lc2;
            float* a = acc[mi][ni];
            if (c0 < MM) {
                if (r0 < MM)
                    *(float2*)&S[(size_t)r0 * MM + c0] = make_float2(a[0], a[1]);
                if (r0 + 8 < MM)
                    *(float2*)&S[(size_t)(r0 + 8) * MM + c0] = make_float2(a[2], a[3]);
                if (bi != bj) {
                    if (r0 < MM) {
                        S[(size_t)c0 * MM + r0] = a[0];
                        S[(size_t)(c0 + 1) * MM + r0] = a[1];
                    }
                    if (r0 + 8 < MM) {
                        S[(size_t)c0 * MM + r0 + 8] = a[2];
                        S[(size_t)(c0 + 1) * MM + r0 + 8] = a[3];
                    }
                }
            }
        }
    }
}

// ---- select: approx top-16 candidate indices per row ------------------------
__global__ __launch_bounds__(256) void select_kernel() {
    int warp = threadIdx.x >> 5, lane = threadIdx.x & 31;
    int row = blockIdx.x * 8 + warp;
    if (row >= NQ * MM) return;
    const float* Srow = g_S + (size_t)row * MM;

    float v[13];
    #pragma unroll
    for (int t = 0; t < 13; t++) {
        int c = lane + t * 32;
        v[t] = (c < MM) ? Srow[c] : -CUDART_INF_F;
    }
    #pragma unroll
    for (int it = 0; it < NCAND; it++) {
        float m = v[0];
        #pragma unroll
        for (int t = 1; t < 13; t++) m = fmaxf(m, v[t]);
        #pragma unroll
        for (int off = 16; off > 0; off >>= 1)
            m = fmaxf(m, __shfl_xor_sync(0xFFFFFFFFu, m, off));
        int c = 0x7FFFFFFF;
        #pragma unroll
        for (int t = 12; t >= 0; t--)
            if (v[t] == m) c = t * 32 + lane;
        #pragma unroll
        for (int off = 16; off > 0; off >>= 1)
            c = min(c, __shfl_xor_sync(0xFFFFFFFFu, c, off));
        if (lane == 0) g_cand[row * NCAND + it] = c;
        #pragma unroll
        for (int t = 0; t < 13; t++)
            if (t * 32 + lane == c) v[t] = -CUDART_INF_F;
    }
}

// ---- exact repair: serial ascending-k fp32 dots for the 16 candidates -------
// One warp per row. Lane l < 16 computes dot(Xs[m], Xs[cand_l]) as ONE serial
// ascending-k fp32 FMA chain (bitwise == reference S entry). Candidate rows
// are consumed in 128-byte chunks (8 consecutive float4, double-buffered) so
// a warp LDG group touches only the 16 minimal cache lines.
__global__ __launch_bounds__(256) void exact_kernel() {
    __shared__ __align__(16) float rowbuf[8][DIM];
    int warp = threadIdx.x >> 5, lane = threadIdx.x & 31;
    int m = blockIdx.x * 8 + warp;
    int q = blockIdx.y;
    int row = q * MM + m;
    const float* Xq = g_Xs + (size_t)q * MPAD * DIM;

    const float4* src = (const float4*)(Xq + (size_t)m * DIM);
    float4* dv = (float4*)rowbuf[warp];
    #pragma unroll
    for (int i = 0; i < 4; i++) dv[lane + 32 * i] = src[lane + 32 * i];
    __syncwarp();

    bool active = (lane < NCAND);
    int ci = active ? g_cand[row * NCAND + lane] : 0;
    const float4* cp = (const float4*)(Xq + (size_t)ci * DIM);
    const float4* rb = (const float4*)rowbuf[warp];

    float acc = 0.0f;
    float4 buf[8], nxt[8];
    if (active) {
        #pragma unroll
        for (int j = 0; j < 8; j++) buf[j] = cp[j];
    }
    #pragma unroll 1
    for (int g = 0; g < 16; g++) {
        if (active && g < 15) {
            #pragma unroll
            for (int j = 0; j < 8; j++) nxt[j] = cp[(g + 1) * 8 + j];
        }
        if (active) {
            #pragma unroll
            for (int j = 0; j < 8; j++) {
                float4 rv = rb[g * 8 + j];      // LDS.128 broadcast
                acc = __fmaf_rn(rv.x, buf[j].x, acc);
                acc = __fmaf_rn(rv.y, buf[j].y, acc);
                acc = __fmaf_rn(rv.z, buf[j].z, acc);
                acc = __fmaf_rn(rv.w, buf[j].w, acc);
            }
            #pragma unroll
            for (int j = 0; j < 8; j++) buf[j] = nxt[j];
        }
    }

    unsigned long long key = active ? pack_key(acc, ci) : 0ULL;
    #pragma unroll
    for (int it = 0; it < KTOP; it++) {
        unsigned long long best = key;
        #pragma unroll
        for (int off = 16; off > 0; off >>= 1) {
            unsigned long long o = __shfl_xor_sync(0xFFFFFFFFu, best, off);
            if (o > best) best = o;
        }
        if (lane == 0) {
            int c = (int)(0xFFFFFFFFu - (unsigned int)(best & 0xFFFFFFFFu));
            g_idx[row * KTOP + it] = c;
            g_vals[row * KTOP + it] = unordf((unsigned int)(best >> 32));
        }
        if (key == best) key = 0ULL;
    }
}

// ---- x_dba + res_top (round-1 proven math) ----------------------------------
__global__ __launch_bounds__(128) void xdba_kernel(const float* __restrict__ Qm,
                                                   float* __restrict__ out, int full) {
    int m = blockIdx.x, q = blockIdx.y, tid = threadIdx.x;
    int row = q * MM + m;
    __shared__ int sidx[KTOP];
    __shared__ float sval[KTOP];
    __shared__ float red[128];
    if (tid < KTOP) {
        sidx[tid] = g_idx[row * KTOP + tid];
        sval[tid] = g_vals[row * KTOP + tid];
    }
    __syncthreads();

    const float4* Xq = (const float4*)(g_Xs + (size_t)q * MPAD * DIM);
    float4 a = Xq[(size_t)sidx[0] * (DIM / 4) + tid];  // w0 = 1.0
    float sumw = 1.0f;
    #pragma unroll
    for (int k = 1; k < KTOP; k++) {
        float w = __fmul_rn(BETA, sval[k]);
        sumw = __fadd_rn(sumw, w);
        float4 v = Xq[(size_t)sidx[k] * (DIM / 4) + tid];
        a.x = __fadd_rn(a.x, __fmul_rn(w, v.x));
        a.y = __fadd_rn(a.y, __fmul_rn(w, v.y));
        a.z = __fadd_rn(a.z, __fmul_rn(w, v.z));
        a.w = __fadd_rn(a.w, __fmul_rn(w, v.w));
    }
    a.x = __fdiv_rn(a.x, sumw);
    a.y = __fdiv_rn(a.y, sumw);
    a.z = __fdiv_rn(a.z, sumw);
    a.w = __fdiv_rn(a.w, sumw);

    if (full)
        *(float4*)(out + OFF_XDBA + (size_t)row * DIM + tid * 4) = a;

    float4 qv = ((const float4*)Qm)[(size_t)q * (DIM / 4) + tid];
    red[tid] = a.x * qv.x + a.y * qv.y + a.z * qv.z + a.w * qv.w;
    __syncthreads();
    #pragma unroll
    for (int s = 64; s > 0; s >>= 1) {
        if (tid < s) red[tid] += red[tid + s];
        __syncthreads();
    }
    if (tid == 0) {
        g_restop[row] = red[0];
        if (full) out[OFF_RESTOP + row] = red[0];
    }
}

// ---- stable descending sort (bitonic 512) + final outputs -------------------
__global__ __launch_bounds__(512) void sort_kernel(float* __restrict__ out,
                                                   int full, int out_size) {
    int q = blockIdx.x, tid = threadIdx.x;
    __shared__ unsigned long long sk[512];
    sk[tid] = (tid < MM) ? pack_key(g_restop[q * MM + tid], tid) : 0ULL;
    __syncthreads();
    for (int k = 2; k <= 512; k <<= 1) {
        for (int j = k >> 1; j > 0; j >>= 1) {
            int ixj = tid ^ j;
            if (ixj > tid) {
                unsigned long long a = sk[tid], b = sk[ixj];
                bool desc = (tid & k) == 0;
                if (desc ? (a < b) : (a > b)) { sk[tid] = b; sk[ixj] = a; }
            }
            __syncthreads();
        }
    }
    if (tid < MM) {
        unsigned int msel = 0xFFFFFFFFu - (unsigned int)(sk[tid] & 0xFFFFFFFFu);
        int o0 = q * MM + tid;
        if (o0 < out_size) out[OFF_RERANK + o0] = (float)g_rt[q * MM + msel];
        if (full) out[OFF_PRE + o0] = (float)msel;
    }
}

extern "C" void kernel_launch(void* const* d_in, const int* in_sizes, int n_in,
                              void* d_out, int out_size) {
    const float* X  = (const float*)d_in[0];
    const float* Qm = (const float*)d_in[1];
    const void*  rk = d_in[2];
    float* out = (float*)d_out;
    int full = (out_size >= FULL_OUT) ? 1 : 0;

    probe_kernel<<<1, 256>>>((const int*)rk);
    gather_kernel<<<dim3(MPAD, NQ), 128>>>(X, rk);
    gemm_kernel<<<dim3(28, NQ), 128>>>();
    select_kernel<<<(NQ * MM + 7) / 8, 256>>>();
    exact_kernel<<<dim3(50, NQ), 256>>>();
    xdba_kernel<<<dim3(MM, NQ), 128>>>(Qm, out, full);
    sort_kernel<<<NQ, 512>>>(out, full, out_size);
}

// round 11
// speedup vs baseline: 1.1309x; 1.1309x over previous
#include <cuda_runtime.h>
#include <cstdint>
#include <math_constants.h>

// ---------------------------------------------------------------------------
// MDescAug: per-query candidate reranking with descriptor augmentation.
//   X: [50000,512] f32,  Q: [100,512] f32,  ranks: [50000,100] i32/i64 (probed)
// Output f32 concat: rerank_final[100,400], res_top[100,400], pre[100,400],
//                    x_dba[100,400,512]
// Strategy: 1-term bf16 tensor GEMM -> approx S (selection only), approx
// top-16 superset (16 needed: bf16 sigma vs min-gap order statistics),
// exact serial-fp32 repair of 16 dots (smem-staged, coalesced) -> bitwise
// reference top-10 -> bitwise-stable downstream.
// ---------------------------------------------------------------------------

#define NDB  50000
#define NQ   100
#define DIM  512
#define MM   400
#define MPAD 448              // 7 * 64, zero-padded rows
#define KTOP 10
#define NCAND 16
#define BETA 0.15f

#define OFF_RERANK 0
#define OFF_RESTOP 40000
#define OFF_PRE    80000
#define OFF_XDBA   120000
#define FULL_OUT   20600000

// Scratch (device globals; no allocation allowed)
__device__ float g_Xs[(size_t)NQ * MPAD * DIM];   // gathered (padded)
__device__ float g_S[(size_t)NQ * MM * MM];       // approx similarity
__device__ int   g_rt[NQ * MM];
__device__ int   g_cand[NQ * MM * NCAND];
__device__ int   g_idx[NQ * MM * KTOP];
__device__ float g_vals[NQ * MM * KTOP];
__device__ float g_restop[NQ * MM];
__device__ int   g_is64;

// ---- order-preserving float<->uint ------------------------------------------
__device__ __forceinline__ unsigned int ordf(float f) {
    unsigned int u = __float_as_uint(f);
    return (u & 0x80000000u) ? ~u : (u | 0x80000000u);
}
__device__ __forceinline__ float unordf(unsigned int o) {
    return __uint_as_float((o & 0x80000000u) ? (o & 0x7FFFFFFFu) : ~o);
}
__device__ __forceinline__ unsigned long long pack_key(float v, int idx) {
    return ((unsigned long long)ordf(v) << 32) |
           (unsigned long long)(0xFFFFFFFFu - (unsigned int)idx);
}

// ---- probe: int64 vs int32 ranks --------------------------------------------
__global__ void probe_kernel(const int* __restrict__ r) {
    __shared__ int cnt;
    if (threadIdx.x == 0) cnt = 0;
    __syncthreads();
    int nz = 0;
    for (int i = threadIdx.x; i < 1024; i += blockDim.x)
        nz += (r[2 * i + 1] != 0);
    atomicAdd(&cnt, nz);
    __syncthreads();
    if (threadIdx.x == 0) g_is64 = (cnt < 100) ? 1 : 0;
}

// ---- gather Xs[q][m][:] = X[ranks[m][q]][:]; zero-pad rows 400..447 ---------
__global__ __launch_bounds__(128) void gather_kernel(const float* __restrict__ X,
                                                     const void* __restrict__ ranks) {
    int m = blockIdx.x, q = blockIdx.y, tid = threadIdx.x;
    float4* dst = (float4*)(g_Xs + ((size_t)q * MPAD + m) * DIM);
    if (m >= MM) {
        dst[tid] = make_float4(0.f, 0.f, 0.f, 0.f);
        return;
    }
    int rid;
    if (g_is64) rid = (int)((const long long*)ranks)[(size_t)m * NQ + q];
    else        rid = ((const int*)ranks)[(size_t)m * NQ + q];
    if (tid == 0) g_rt[q * MM + m] = rid;
    const float4* src = (const float4*)(X + (size_t)rid * DIM);
    dst[tid] = src[tid];
}

// ---- bf16 pack: (x0, x1) -> bf16x2 ------------------------------------------
__device__ __forceinline__ unsigned cvt_bf2(float x0, float x1) {
    unsigned h;
    asm("cvt.rn.bf16x2.f32 %0, %1, %2;" : "=r"(h) : "f"(x1), "f"(x0));
    return h;
}

__device__ __forceinline__ void mma_bf16(float* c, const unsigned* a, const unsigned* b) {
    asm volatile(
        "mma.sync.aligned.m16n8k16.row.col.f32.bf16.bf16.f32 "
        "{%0,%1,%2,%3}, {%4,%5,%6,%7}, {%8,%9}, {%0,%1,%2,%3};\n"
        : "+f"(c[0]), "+f"(c[1]), "+f"(c[2]), "+f"(c[3])
        : "r"(a[0]), "r"(a[1]), "r"(a[2]), "r"(a[3]), "r"(b[0]), "r"(b[1]));
}

// ---- batched symmetric approx GEMM, plain bf16 ------------------------------
// Block tile 64x64, BK=32, 128 threads (4 warps, 2x2 of 32x32 warp tiles).
// Staging is row-grouped/coalesced: each warp LDG touches 4 cache lines.
#define LDW 18   // smem row stride in 32-bit words (36 halves); conflict-free
__global__ __launch_bounds__(128) void gemm_kernel() {
    __shared__ unsigned Ah[64 * LDW];
    __shared__ unsigned Bh[64 * LDW];

    int p = blockIdx.x, q = blockIdx.y;
    int bi = 0, bj = 0;
    {
        int t = 0;
        #pragma unroll
        for (int i = 0; i < 7; i++) {
            int c = 7 - i;
            if (p < t + c) { bi = i; bj = i + (p - t); break; }
            t += c;
        }
    }
    const float* Xq = g_Xs + (size_t)q * MPAD * DIM;
    const float* Ap = Xq + (size_t)bi * 64 * DIM;
    const float* Bp = Xq + (size_t)bj * 64 * DIM;

    int tid = threadIdx.x;
    int warp = tid >> 5, lane = tid & 31;
    int wm = warp >> 1, wn = warp & 1;
    int lr = lane >> 2, lc = lane & 3;

    // coalesced staging mapping: i=0..3 -> row = i*16 + (tid>>3), f4-col = tid&7
    int r0s = tid >> 3, c0s = tid & 7;

    float acc[2][4][4];
    #pragma unroll
    for (int mi = 0; mi < 2; mi++)
        #pragma unroll
        for (int ni = 0; ni < 4; ni++)
            #pragma unroll
            for (int e = 0; e < 4; e++) acc[mi][ni][e] = 0.0f;

    float4 pA[4], pB[4];
    #pragma unroll
    for (int i = 0; i < 4; i++) {
        pA[i] = *(const float4*)(Ap + (size_t)(i * 16 + r0s) * DIM + c0s * 4);
        pB[i] = *(const float4*)(Bp + (size_t)(i * 16 + r0s) * DIM + c0s * 4);
    }

    for (int ch = 0; ch < 16; ch++) {
        __syncthreads();
        #pragma unroll
        for (int i = 0; i < 4; i++) {
            int w = (i * 16 + r0s) * LDW + 2 * c0s;
            Ah[w]     = cvt_bf2(pA[i].x, pA[i].y);
            Ah[w + 1] = cvt_bf2(pA[i].z, pA[i].w);
            Bh[w]     = cvt_bf2(pB[i].x, pB[i].y);
            Bh[w + 1] = cvt_bf2(pB[i].z, pB[i].w);
        }
        __syncthreads();
        if (ch < 15) {
            int o = (ch + 1) * 32;
            #pragma unroll
            for (int i = 0; i < 4; i++) {
                pA[i] = *(const float4*)(Ap + (size_t)(i * 16 + r0s) * DIM + o + c0s * 4);
                pB[i] = *(const float4*)(Bp + (size_t)(i * 16 + r0s) * DIM + o + c0s * 4);
            }
        }
        #pragma unroll
        for (int kc = 0; kc < 2; kc++) {
            int cb = kc * 8 + lc;
            unsigned ah[2][4];
            #pragma unroll
            for (int mi = 0; mi < 2; mi++) {
                int r = wm * 32 + mi * 16 + lr;
                ah[mi][0] = Ah[r * LDW + cb];
                ah[mi][1] = Ah[(r + 8) * LDW + cb];
                ah[mi][2] = Ah[r * LDW + cb + 4];
                ah[mi][3] = Ah[(r + 8) * LDW + cb + 4];
            }
            #pragma unroll
            for (int ni = 0; ni < 4; ni++) {
                int n = wn * 32 + ni * 8 + lr;
                unsigned bh[2] = {Bh[n * LDW + cb], Bh[n * LDW + cb + 4]};
                #pragma unroll
                for (int mi = 0; mi < 2; mi++)
                    mma_bf16(acc[mi][ni], ah[mi], bh);
            }
        }
    }

    float* S = g_S + (size_t)q * MM * MM;
    int lc2 = lc * 2;
    #pragma unroll
    for (int mi = 0; mi < 2; mi++) {
        #pragma unroll
        for (int ni = 0; ni < 4; ni++) {
            int r0 = bi * 64 + wm * 32 + mi * 16 + lr;
            int c0 = bj * 64 + wn * 32 + ni * 8 + lc2;
            float* a = acc[mi][ni];
            if (c0 < MM) {
                if (r0 < MM)
                    *(float2*)&S[(size_t)r0 * MM + c0] = make_float2(a[0], a[1]);
                if (r0 + 8 < MM)
                    *(float2*)&S[(size_t)(r0 + 8) * MM + c0] = make_float2(a[2], a[3]);
                if (bi != bj) {
                    if (r0 < MM) {
                        S[(size_t)c0 * MM + r0] = a[0];
                        S[(size_t)(c0 + 1) * MM + r0] = a[1];
                    }
                    if (r0 + 8 < MM) {
                        S[(size_t)c0 * MM + r0 + 8] = a[2];
                        S[(size_t)(c0 + 1) * MM + r0 + 8] = a[3];
                    }
                }
            }
        }
    }
}

// ---- select: approx top-16 candidate indices per row ------------------------
__global__ __launch_bounds__(256) void select_kernel() {
    int warp = threadIdx.x >> 5, lane = threadIdx.x & 31;
    int row = blockIdx.x * 8 + warp;
    if (row >= NQ * MM) return;
    const float* Srow = g_S + (size_t)row * MM;

    float v[13];
    #pragma unroll
    for (int t = 0; t < 13; t++) {
        int c = lane + t * 32;
        v[t] = (c < MM) ? Srow[c] : -CUDART_INF_F;
    }
    #pragma unroll
    for (int it = 0; it < NCAND; it++) {
        float m = v[0];
        #pragma unroll
        for (int t = 1; t < 13; t++) m = fmaxf(m, v[t]);
        #pragma unroll
        for (int off = 16; off > 0; off >>= 1)
            m = fmaxf(m, __shfl_xor_sync(0xFFFFFFFFu, m, off));
        int c = 0x7FFFFFFF;
        #pragma unroll
        for (int t = 12; t >= 0; t--)
            if (v[t] == m) c = t * 32 + lane;
        #pragma unroll
        for (int off = 16; off > 0; off >>= 1)
            c = min(c, __shfl_xor_sync(0xFFFFFFFFu, c, off));
        if (lane == 0) g_cand[row * NCAND + it] = c;
        #pragma unroll
        for (int t = 0; t < 13; t++)
            if (t * 32 + lane == c) v[t] = -CUDART_INF_F;
    }
}

// ---- exact repair: smem-staged serial ascending-k fp32 dots -----------------
// One 128-thread block per row. All warps stage the 16 candidate rows + the
// m-row coalesced (4 lines per warp LDG). A rotating compute warp runs the
// 16 serial fp32 FMA chains (bitwise == reference S entries), then top-10.
#define CSTRIDE 129   // float4 stride per candidate row (bank-spread)
__global__ __launch_bounds__(128) void exact_kernel() {
    __shared__ __align__(16) float4 cbuf[NCAND * CSTRIDE];
    __shared__ __align__(16) float4 mbuf[DIM / 4];
    __shared__ int scand[NCAND];
    int m = blockIdx.x, q = blockIdx.y, tid = threadIdx.x;
    int wid = tid >> 5, lane = tid & 31;
    int row = q * MM + m;
    const float* Xq = g_Xs + (size_t)q * MPAD * DIM;

    if (tid < NCAND) scand[tid] = g_cand[row * NCAND + tid];
    mbuf[tid] = ((const float4*)(Xq + (size_t)m * DIM))[tid];
    __syncthreads();
    #pragma unroll
    for (int i = 0; i < NCAND; i++)
        cbuf[i * CSTRIDE + tid] = ((const float4*)(Xq + (size_t)scand[i] * DIM))[tid];
    __syncthreads();

    if (wid == (blockIdx.x & 3)) {     // rotate compute warp across SMSPs
        bool act = lane < NCAND;
        int ci = act ? scand[lane] : 0;
        const float4* cp = &cbuf[(act ? lane : 0) * CSTRIDE];
        float acc = 0.0f;
        #pragma unroll 4
        for (int k4 = 0; k4 < DIM / 4; k4++) {
            float4 rv = mbuf[k4];
            float4 cv = cp[k4];
            acc = __fmaf_rn(rv.x, cv.x, acc);
            acc = __fmaf_rn(rv.y, cv.y, acc);
            acc = __fmaf_rn(rv.z, cv.z, acc);
            acc = __fmaf_rn(rv.w, cv.w, acc);
        }
        unsigned long long key = act ? pack_key(acc, ci) : 0ULL;
        #pragma unroll
        for (int it = 0; it < KTOP; it++) {
            unsigned long long best = key;
            #pragma unroll
            for (int off = 16; off > 0; off >>= 1) {
                unsigned long long o = __shfl_xor_sync(0xFFFFFFFFu, best, off);
                if (o > best) best = o;
            }
            if (lane == 0) {
                int c = (int)(0xFFFFFFFFu - (unsigned int)(best & 0xFFFFFFFFu));
                g_idx[row * KTOP + it] = c;
                g_vals[row * KTOP + it] = unordf((unsigned int)(best >> 32));
            }
            if (key == best) key = 0ULL;
        }
    }
}

// ---- x_dba + res_top (round-1 proven math) ----------------------------------
__global__ __launch_bounds__(128) void xdba_kernel(const float* __restrict__ Qm,
                                                   float* __restrict__ out, int full) {
    int m = blockIdx.x, q = blockIdx.y, tid = threadIdx.x;
    int row = q * MM + m;
    __shared__ int sidx[KTOP];
    __shared__ float sval[KTOP];
    __shared__ float red[128];
    if (tid < KTOP) {
        sidx[tid] = g_idx[row * KTOP + tid];
        sval[tid] = g_vals[row * KTOP + tid];
    }
    __syncthreads();

    const float4* Xq = (const float4*)(g_Xs + (size_t)q * MPAD * DIM);
    float4 a = Xq[(size_t)sidx[0] * (DIM / 4) + tid];  // w0 = 1.0
    float sumw = 1.0f;
    #pragma unroll
    for (int k = 1; k < KTOP; k++) {
        float w = __fmul_rn(BETA, sval[k]);
        sumw = __fadd_rn(sumw, w);
        float4 v = Xq[(size_t)sidx[k] * (DIM / 4) + tid];
        a.x = __fadd_rn(a.x, __fmul_rn(w, v.x));
        a.y = __fadd_rn(a.y, __fmul_rn(w, v.y));
        a.z = __fadd_rn(a.z, __fmul_rn(w, v.z));
        a.w = __fadd_rn(a.w, __fmul_rn(w, v.w));
    }
    a.x = __fdiv_rn(a.x, sumw);
    a.y = __fdiv_rn(a.y, sumw);
    a.z = __fdiv_rn(a.z, sumw);
    a.w = __fdiv_rn(a.w, sumw);

    if (full)
        *(float4*)(out + OFF_XDBA + (size_t)row * DIM + tid * 4) = a;

    float4 qv = ((const float4*)Qm)[(size_t)q * (DIM / 4) + tid];
    red[tid] = a.x * qv.x + a.y * qv.y + a.z * qv.z + a.w * qv.w;
    __syncthreads();
    #pragma unroll
    for (int s = 64; s > 0; s >>= 1) {
        if (tid < s) red[tid] += red[tid + s];
        __syncthreads();
    }
    if (tid == 0) {
        g_restop[row] = red[0];
        if (full) out[OFF_RESTOP + row] = red[0];
    }
}

// ---- stable descending sort (bitonic 512) + final outputs -------------------
__global__ __launch_bounds__(512) void sort_kernel(float* __restrict__ out,
                                                   int full, int out_size) {
    int q = blockIdx.x, tid = threadIdx.x;
    __shared__ unsigned long long sk[512];
    sk[tid] = (tid < MM) ? pack_key(g_restop[q * MM + tid], tid) : 0ULL;
    __syncthreads();
    for (int k = 2; k <= 512; k <<= 1) {
        for (int j = k >> 1; j > 0; j >>= 1) {
            int ixj = tid ^ j;
            if (ixj > tid) {
                unsigned long long a = sk[tid], b = sk[ixj];
                bool desc = (tid & k) == 0;
                if (desc ? (a < b) : (a > b)) { sk[tid] = b; sk[ixj] = a; }
            }
            __syncthreads();
        }
    }
    if (tid < MM) {
        unsigned int msel = 0xFFFFFFFFu - (unsigned int)(sk[tid] & 0xFFFFFFFFu);
        int o0 = q * MM + tid;
        if (o0 < out_size) out[OFF_RERANK + o0] = (float)g_rt[q * MM + msel];
        if (full) out[OFF_PRE + o0] = (float)msel;
    }
}

extern "C" void kernel_launch(void* const* d_in, const int* in_sizes, int n_in,
                              void* d_out, int out_size) {
    const float* X  = (const float*)d_in[0];
    const float* Qm = (const float*)d_in[1];
    const void*  rk = d_in[2];
    float* out = (float*)d_out;
    int full = (out_size >= FULL_OUT) ? 1 : 0;

    probe_kernel<<<1, 256>>>((const int*)rk);
    gather_kernel<<<dim3(MPAD, NQ), 128>>>(X, rk);
    gemm_kernel<<<dim3(28, NQ), 128>>>();
    select_kernel<<<(NQ * MM + 7) / 8, 256>>>();
    exact_kernel<<<dim3(MM, NQ), 128>>>();
    xdba_kernel<<<dim3(MM, NQ), 128>>>(Qm, out, full);
    sort_kernel<<<NQ, 512>>>(out, full, out_size);
}

// round 12
// speedup vs baseline: 1.1409x; 1.0088x over previous
#include <cuda_runtime.h>
#include <cstdint>
#include <math_constants.h>

// ---------------------------------------------------------------------------
// MDescAug: per-query candidate reranking with descriptor augmentation.
//   X: [50000,512] f32,  Q: [100,512] f32,  ranks: [50000,100] i32/i64 (probed)
// Output f32 concat: rerank_final[100,400], res_top[100,400], pre[100,400],
//                    x_dba[100,400,512]
// Strategy: 1-term bf16 tensor GEMM -> approx S (selection only), approx
// top-16 superset, exact serial-fp32 repair of 16 dots (smem-staged) ->
// bitwise reference top-10, with x_dba/res_top FUSED into the same kernel
// (rows already in smem) -> bitwise-stable downstream.
// ---------------------------------------------------------------------------

#define NDB  50000
#define NQ   100
#define DIM  512
#define MM   400
#define MPAD 448              // 7 * 64, zero-padded rows
#define KTOP 10
#define NCAND 16
#define BETA 0.15f

#define OFF_RERANK 0
#define OFF_RESTOP 40000
#define OFF_PRE    80000
#define OFF_XDBA   120000
#define FULL_OUT   20600000

// Scratch (device globals; no allocation allowed)
__device__ float g_Xs[(size_t)NQ * MPAD * DIM];   // gathered (padded)
__device__ float g_S[(size_t)NQ * MM * MM];       // approx similarity
__device__ int   g_rt[NQ * MM];
__device__ int   g_cand[NQ * MM * NCAND];
__device__ float g_restop[NQ * MM];
__device__ int   g_is64;

// ---- order-preserving float<->uint ------------------------------------------
__device__ __forceinline__ unsigned int ordf(float f) {
    unsigned int u = __float_as_uint(f);
    return (u & 0x80000000u) ? ~u : (u | 0x80000000u);
}
__device__ __forceinline__ float unordf(unsigned int o) {
    return __uint_as_float((o & 0x80000000u) ? (o & 0x7FFFFFFFu) : ~o);
}
__device__ __forceinline__ unsigned long long pack_key(float v, int idx) {
    return ((unsigned long long)ordf(v) << 32) |
           (unsigned long long)(0xFFFFFFFFu - (unsigned int)idx);
}

// ---- probe: int64 vs int32 ranks --------------------------------------------
__global__ void probe_kernel(const int* __restrict__ r) {
    __shared__ int cnt;
    if (threadIdx.x == 0) cnt = 0;
    __syncthreads();
    int nz = 0;
    for (int i = threadIdx.x; i < 1024; i += blockDim.x)
        nz += (r[2 * i + 1] != 0);
    atomicAdd(&cnt, nz);
    __syncthreads();
    if (threadIdx.x == 0) g_is64 = (cnt < 100) ? 1 : 0;
}

// ---- gather Xs[q][m][:] = X[ranks[m][q]][:]; zero-pad rows 400..447 ---------
__global__ __launch_bounds__(128) void gather_kernel(const float* __restrict__ X,
                                                     const void* __restrict__ ranks) {
    int m = blockIdx.x, q = blockIdx.y, tid = threadIdx.x;
    float4* dst = (float4*)(g_Xs + ((size_t)q * MPAD + m) * DIM);
    if (m >= MM) {
        dst[tid] = make_float4(0.f, 0.f, 0.f, 0.f);
        return;
    }
    int rid;
    if (g_is64) rid = (int)((const long long*)ranks)[(size_t)m * NQ + q];
    else        rid = ((const int*)ranks)[(size_t)m * NQ + q];
    if (tid == 0) g_rt[q * MM + m] = rid;
    const float4* src = (const float4*)(X + (size_t)rid * DIM);
    dst[tid] = src[tid];
}

// ---- bf16 pack: (x0, x1) -> bf16x2 ------------------------------------------
__device__ __forceinline__ unsigned cvt_bf2(float x0, float x1) {
    unsigned h;
    asm("cvt.rn.bf16x2.f32 %0, %1, %2;" : "=r"(h) : "f"(x1), "f"(x0));
    return h;
}

__device__ __forceinline__ void mma_bf16(float* c, const unsigned* a, const unsigned* b) {
    asm volatile(
        "mma.sync.aligned.m16n8k16.row.col.f32.bf16.bf16.f32 "
        "{%0,%1,%2,%3}, {%4,%5,%6,%7}, {%8,%9}, {%0,%1,%2,%3};\n"
        : "+f"(c[0]), "+f"(c[1]), "+f"(c[2]), "+f"(c[3])
        : "r"(a[0]), "r"(a[1]), "r"(a[2]), "r"(a[3]), "r"(b[0]), "r"(b[1]));
}

// ---- batched symmetric approx GEMM, plain bf16 ------------------------------
// Block tile 64x64, BK=32, 128 threads (4 warps, 2x2 of 32x32 warp tiles).
#define LDW 18   // smem row stride in 32-bit words (36 halves); conflict-free
__global__ __launch_bounds__(128) void gemm_kernel() {
    __shared__ unsigned Ah[64 * LDW];
    __shared__ unsigned Bh[64 * LDW];

    int p = blockIdx.x, q = blockIdx.y;
    int bi = 0, bj = 0;
    {
        int t = 0;
        #pragma unroll
        for (int i = 0; i < 7; i++) {
            int c = 7 - i;
            if (p < t + c) { bi = i; bj = i + (p - t); break; }
            t += c;
        }
    }
    const float* Xq = g_Xs + (size_t)q * MPAD * DIM;
    const float* Ap = Xq + (size_t)bi * 64 * DIM;
    const float* Bp = Xq + (size_t)bj * 64 * DIM;

    int tid = threadIdx.x;
    int warp = tid >> 5, lane = tid & 31;
    int wm = warp >> 1, wn = warp & 1;
    int lr = lane >> 2, lc = lane & 3;

    // coalesced staging mapping: i=0..3 -> row = i*16 + (tid>>3), f4-col = tid&7
    int r0s = tid >> 3, c0s = tid & 7;

    float acc[2][4][4];
    #pragma unroll
    for (int mi = 0; mi < 2; mi++)
        #pragma unroll
        for (int ni = 0; ni < 4; ni++)
            #pragma unroll
            for (int e = 0; e < 4; e++) acc[mi][ni][e] = 0.0f;

    float4 pA[4], pB[4];
    #pragma unroll
    for (int i = 0; i < 4; i++) {
        pA[i] = *(const float4*)(Ap + (size_t)(i * 16 + r0s) * DIM + c0s * 4);
        pB[i] = *(const float4*)(Bp + (size_t)(i * 16 + r0s) * DIM + c0s * 4);
    }

    for (int ch = 0; ch < 16; ch++) {
        __syncthreads();
        #pragma unroll
        for (int i = 0; i < 4; i++) {
            int w = (i * 16 + r0s) * LDW + 2 * c0s;
            Ah[w]     = cvt_bf2(pA[i].x, pA[i].y);
            Ah[w + 1] = cvt_bf2(pA[i].z, pA[i].w);
            Bh[w]     = cvt_bf2(pB[i].x, pB[i].y);
            Bh[w + 1] = cvt_bf2(pB[i].z, pB[i].w);
        }
        __syncthreads();
        if (ch < 15) {
            int o = (ch + 1) * 32;
            #pragma unroll
            for (int i = 0; i < 4; i++) {
                pA[i] = *(const float4*)(Ap + (size_t)(i * 16 + r0s) * DIM + o + c0s * 4);
                pB[i] = *(const float4*)(Bp + (size_t)(i * 16 + r0s) * DIM + o + c0s * 4);
            }
        }
        #pragma unroll
        for (int kc = 0; kc < 2; kc++) {
            int cb = kc * 8 + lc;
            unsigned ah[2][4];
            #pragma unroll
            for (int mi = 0; mi < 2; mi++) {
                int r = wm * 32 + mi * 16 + lr;
                ah[mi][0] = Ah[r * LDW + cb];
                ah[mi][1] = Ah[(r + 8) * LDW + cb];
                ah[mi][2] = Ah[r * LDW + cb + 4];
                ah[mi][3] = Ah[(r + 8) * LDW + cb + 4];
            }
            #pragma unroll
            for (int ni = 0; ni < 4; ni++) {
                int n = wn * 32 + ni * 8 + lr;
                unsigned bh[2] = {Bh[n * LDW + cb], Bh[n * LDW + cb + 4]};
                #pragma unroll
                for (int mi = 0; mi < 2; mi++)
                    mma_bf16(acc[mi][ni], ah[mi], bh);
            }
        }
    }

    float* S = g_S + (size_t)q * MM * MM;
    int lc2 = lc * 2;
    #pragma unroll
    for (int mi = 0; mi < 2; mi++) {
        #pragma unroll
        for (int ni = 0; ni < 4; ni++) {
            int r0 = bi * 64 + wm * 32 + mi * 16 + lr;
            int c0 = bj * 64 + wn * 32 + ni * 8 + lc2;
            float* a = acc[mi][ni];
            if (c0 < MM) {
                if (r0 < MM)
                    *(float2*)&S[(size_t)r0 * MM + c0] = make_float2(a[0], a[1]);
                if (r0 + 8 < MM)
                    *(float2*)&S[(size_t)(r0 + 8) * MM + c0] = make_float2(a[2], a[3]);
                if (bi != bj) {
                    if (r0 < MM) {
                        S[(size_t)c0 * MM + r0] = a[0];
                        S[(size_t)(c0 + 1) * MM + r0] = a[1];
                    }
                    if (r0 + 8 < MM) {
                        S[(size_t)c0 * MM + r0 + 8] = a[2];
                        S[(size_t)(c0 + 1) * MM + r0 + 8] = a[3];
                    }
                }
            }
        }
    }
}

// ---- select: approx top-16 candidate indices per row ------------------------
__global__ __launch_bounds__(256) void select_kernel() {
    int warp = threadIdx.x >> 5, lane = threadIdx.x & 31;
    int row = blockIdx.x * 8 + warp;
    if (row >= NQ * MM) return;
    const float* Srow = g_S + (size_t)row * MM;

    float v[13];
    #pragma unroll
    for (int t = 0; t < 13; t++) {
        int c = lane + t * 32;
        v[t] = (c < MM) ? Srow[c] : -CUDART_INF_F;
    }
    #pragma unroll
    for (int it = 0; it < NCAND; it++) {
        float m = v[0];
        #pragma unroll
        for (int t = 1; t < 13; t++) m = fmaxf(m, v[t]);
        #pragma unroll
        for (int off = 16; off > 0; off >>= 1)
            m = fmaxf(m, __shfl_xor_sync(0xFFFFFFFFu, m, off));
        int c = 0x7FFFFFFF;
        #pragma unroll
        for (int t = 12; t >= 0; t--)
            if (v[t] == m) c = t * 32 + lane;
        #pragma unroll
        for (int off = 16; off > 0; off >>= 1)
            c = min(c, __shfl_xor_sync(0xFFFFFFFFu, c, off));
        if (lane == 0) g_cand[row * NCAND + it] = c;
        #pragma unroll
        for (int t = 0; t < 13; t++)
            if (t * 32 + lane == c) v[t] = -CUDART_INF_F;
    }
}

// ---- exact repair + FUSED x_dba/res_top -------------------------------------
// One 128-thread block per row. All warps stage the 16 candidate rows + the
// m-row (coalesced). A rotating compute warp runs 16 serial ascending-k fp32
// FMA chains (bitwise == reference S entries) and selects top-10 by
// (value desc, index asc), publishing (slot, val). Then ALL threads compute
// x_dba and res_top straight from the smem-resident rows (bitwise-identical
// arithmetic to the previous standalone xdba kernel).
#define CSTRIDE 129   // float4 stride per candidate row (bank-spread)
__global__ __launch_bounds__(128) void exact_kernel(const float* __restrict__ Qm,
                                                    float* __restrict__ out, int full) {
    __shared__ __align__(16) float4 cbuf[NCAND * CSTRIDE];
    __shared__ __align__(16) float4 mbuf[DIM / 4];
    __shared__ int scand[NCAND];
    __shared__ int sslot[KTOP];
    __shared__ float ssval[KTOP];
    __shared__ float red[128];
    int m = blockIdx.x, q = blockIdx.y, tid = threadIdx.x;
    int wid = tid >> 5, lane = tid & 31;
    int row = q * MM + m;
    const float* Xq = g_Xs + (size_t)q * MPAD * DIM;

    if (tid < NCAND) scand[tid] = g_cand[row * NCAND + tid];
    mbuf[tid] = ((const float4*)(Xq + (size_t)m * DIM))[tid];
    __syncthreads();
    #pragma unroll
    for (int i = 0; i < NCAND; i++)
        cbuf[i * CSTRIDE + tid] = ((const float4*)(Xq + (size_t)scand[i] * DIM))[tid];
    __syncthreads();

    if (wid == (blockIdx.x & 3)) {     // rotate compute warp across SMSPs
        bool act = lane < NCAND;
        int ci = act ? scand[lane] : 0;
        const float4* cp = &cbuf[(act ? lane : 0) * CSTRIDE];
        float acc = 0.0f;
        #pragma unroll 4
        for (int k4 = 0; k4 < DIM / 4; k4++) {
            float4 rv = mbuf[k4];
            float4 cv = cp[k4];
            acc = __fmaf_rn(rv.x, cv.x, acc);
            acc = __fmaf_rn(rv.y, cv.y, acc);
            acc = __fmaf_rn(rv.z, cv.z, acc);
            acc = __fmaf_rn(rv.w, cv.w, acc);
        }
        unsigned long long key = act ? pack_key(acc, ci) : 0ULL;
        #pragma unroll
        for (int it = 0; it < KTOP; it++) {
            unsigned long long best = key;
            #pragma unroll
            for (int off = 16; off > 0; off >>= 1) {
                unsigned long long o = __shfl_xor_sync(0xFFFFFFFFu, best, off);
                if (o > best) best = o;
            }
            int c = (int)(0xFFFFFFFFu - (unsigned int)(best & 0xFFFFFFFFu));
            // find a smem slot holding global index c (dup rows are identical)
            unsigned bal = __ballot_sync(0xFFFFFFFFu, act && ci == c);
            if (lane == 0) {
                sslot[it] = __ffs(bal) - 1;
                ssval[it] = unordf((unsigned int)(best >> 32));
            }
            if (key == best) key = 0ULL;
        }
    }
    __syncthreads();

    // fused x_dba + res_top (byte-identical math to prior xdba kernel)
    float4 a = cbuf[(size_t)sslot[0] * CSTRIDE + tid];   // w0 = 1.0
    float sumw = 1.0f;
    #pragma unroll
    for (int k = 1; k < KTOP; k++) {
        float w = __fmul_rn(BETA, ssval[k]);
        sumw = __fadd_rn(sumw, w);
        float4 v = cbuf[(size_t)sslot[k] * CSTRIDE + tid];
        a.x = __fadd_rn(a.x, __fmul_rn(w, v.x));
        a.y = __fadd_rn(a.y, __fmul_rn(w, v.y));
        a.z = __fadd_rn(a.z, __fmul_rn(w, v.z));
        a.w = __fadd_rn(a.w, __fmul_rn(w, v.w));
    }
    a.x = __fdiv_rn(a.x, sumw);
    a.y = __fdiv_rn(a.y, sumw);
    a.z = __fdiv_rn(a.z, sumw);
    a.w = __fdiv_rn(a.w, sumw);

    if (full)
        *(float4*)(out + OFF_XDBA + (size_t)row * DIM + tid * 4) = a;

    float4 qv = ((const float4*)Qm)[(size_t)q * (DIM / 4) + tid];
    red[tid] = a.x * qv.x + a.y * qv.y + a.z * qv.z + a.w * qv.w;
    __syncthreads();
    #pragma unroll
    for (int s = 64; s > 0; s >>= 1) {
        if (tid < s) red[tid] += red[tid + s];
        __syncthreads();
    }
    if (tid == 0) {
        g_restop[row] = red[0];
        if (full) out[OFF_RESTOP + row] = red[0];
    }
}

// ---- stable descending sort (bitonic 512) + final outputs -------------------
__global__ __launch_bounds__(512) void sort_kernel(float* __restrict__ out,
                                                   int full, int out_size) {
    int q = blockIdx.x, tid = threadIdx.x;
    __shared__ unsigned long long sk[512];
    sk[tid] = (tid < MM) ? pack_key(g_restop[q * MM + tid], tid) : 0ULL;
    __syncthreads();
    for (int k = 2; k <= 512; k <<= 1) {
        for (int j = k >> 1; j > 0; j >>= 1) {
            int ixj = tid ^ j;
            if (ixj > tid) {
                unsigned long long a = sk[tid], b = sk[ixj];
                bool desc = (tid & k) == 0;
                if (desc ? (a < b) : (a > b)) { sk[tid] = b; sk[ixj] = a; }
            }
            __syncthreads();
        }
    }
    if (tid < MM) {
        unsigned int msel = 0xFFFFFFFFu - (unsigned int)(sk[tid] & 0xFFFFFFFFu);
        int o0 = q * MM + tid;
        if (o0 < out_size) out[OFF_RERANK + o0] = (float)g_rt[q * MM + msel];
        if (full) out[OFF_PRE + o0] = (float)msel;
    }
}

extern "C" void kernel_launch(void* const* d_in, const int* in_sizes, int n_in,
                              void* d_out, int out_size) {
    const float* X  = (const float*)d_in[0];
    const float* Qm = (const float*)d_in[1];
    const void*  rk = d_in[2];
    float* out = (float*)d_out;
    int full = (out_size >= FULL_OUT) ? 1 : 0;

    probe_kernel<<<1, 256>>>((const int*)rk);
    gather_kernel<<<dim3(MPAD, NQ), 128>>>(X, rk);
    gemm_kernel<<<dim3(28, NQ), 128>>>();
    select_kernel<<<(NQ * MM + 7) / 8, 256>>>();
    exact_kernel<<<dim3(MM, NQ), 128>>>(Qm, out, full);
    sort_kernel<<<NQ, 512>>>(out, full, out_size);
}